// round 3
// baseline (speedup 1.0000x reference)
#include <cuda_runtime.h>

// DeepPoly ReLU relaxation, elementwise over N floats.
// inputs: lb, ub, alpha (fp32, N each). output: [out_lb (N) | out_ub (N)] fp32.
//
// HBM-bound: 20 B/elem mandatory traffic (3 reads + 2 writes).
// 2x float4 per thread, streaming cache hints (single-touch data).

#define QUADS_PER_THREAD 2

__global__ __launch_bounds__(256) void verify_relu_kernel(
    const float4* __restrict__ lb4,
    const float4* __restrict__ ub4,
    const float4* __restrict__ al4,
    float4* __restrict__ olb4,
    float4* __restrict__ oub4,
    int n4)
{
    int base = blockIdx.x * (256 * QUADS_PER_THREAD) + threadIdx.x;

    float4 lb[QUADS_PER_THREAD], ub[QUADS_PER_THREAD], al[QUADS_PER_THREAD];

    // front-batched streaming loads (evict-first; data is single-touch)
    #pragma unroll
    for (int q = 0; q < QUADS_PER_THREAD; q++) {
        int i = base + q * 256;
        lb[q] = __ldcs(&lb4[i]);
        ub[q] = __ldcs(&ub4[i]);
        al[q] = __ldcs(&al4[i]);
    }

    #pragma unroll
    for (int q = 0; q < QUADS_PER_THREAD; q++) {
        int i = base + q * 256;
        float4 olb, oub;
        #pragma unroll
        for (int k = 0; k < 4; k++) {
            float l = (&lb[q].x)[k];
            float u = (&ub[q].x)[k];
            float a = (&al[q].x)[k];

            float ca    = fminf(fmaxf(a, 0.0f), 1.0f);
            float slope = fmaxf(u / (u - l), 0.0f);

            float uc_diag = (l > 0.0f) ? 1.0f : slope;
            float uc_bias = (l > 0.0f) ? 0.0f : (-(slope * l));
            float lc_diag = (u < 0.0f) ? 0.0f : ca;

            (&olb.x)[k] = l * lc_diag;
            (&oub.x)[k] = fmaf(u, uc_diag, uc_bias);
        }
        __stcs(&olb4[i], olb);
        __stcs(&oub4[i], oub);
    }
}

extern "C" void kernel_launch(void* const* d_in, const int* in_sizes, int n_in,
                              void* d_out, int out_size) {
    const float* lb    = (const float*)d_in[0];
    const float* ub    = (const float*)d_in[1];
    const float* alpha = (const float*)d_in[2];
    float* out = (float*)d_out;

    int n  = in_sizes[0];        // 16777216
    int n4 = n / 4;              // 4194304 (divisible)

    float* out_lb = out;
    float* out_ub = out + n;

    int threads = 256;
    int quads_per_block = threads * QUADS_PER_THREAD;   // 512
    int blocks = n4 / quads_per_block;                  // 8192, exact

    verify_relu_kernel<<<blocks, threads>>>(
        (const float4*)lb, (const float4*)ub, (const float4*)alpha,
        (float4*)out_lb, (float4*)out_ub, n4);
}

// round 4
// speedup vs baseline: 1.0054x; 1.0054x over previous
#include <cuda_runtime.h>

// DeepPoly ReLU relaxation, elementwise over N floats.
// inputs: lb, ub, alpha (fp32, N each). output: [out_lb (N) | out_ub (N)] fp32.
//
// HBM-bound: 20 B/elem mandatory traffic (3 reads + 2 writes) = 336 MB.
// R1 shape (1 float4/thread, 256 thr, occ ~80%) + streaming cache policy:
// data is single-touch, so evict-first loads / streaming stores keep the
// 336 MB stream from churning the 126 MB L2.

__global__ __launch_bounds__(256) void verify_relu_kernel(
    const float4* __restrict__ lb4,
    const float4* __restrict__ ub4,
    const float4* __restrict__ al4,
    float4* __restrict__ olb4,
    float4* __restrict__ oub4,
    int n4)
{
    int i = blockIdx.x * blockDim.x + threadIdx.x;
    if (i >= n4) return;

    float4 lb = __ldcs(&lb4[i]);
    float4 ub = __ldcs(&ub4[i]);
    float4 al = __ldcs(&al4[i]);

    float4 olb, oub;

    #pragma unroll
    for (int k = 0; k < 4; k++) {
        float l = (&lb.x)[k];
        float u = (&ub.x)[k];
        float a = (&al.x)[k];

        float ca    = fminf(fmaxf(a, 0.0f), 1.0f);
        float slope = fmaxf(u / (u - l), 0.0f);

        float uc_diag = (l > 0.0f) ? 1.0f : slope;
        float uc_bias = (l > 0.0f) ? 0.0f : (-(slope * l));
        float lc_diag = (u < 0.0f) ? 0.0f : ca;

        (&olb.x)[k] = l * lc_diag;
        (&oub.x)[k] = fmaf(u, uc_diag, uc_bias);
    }

    __stcs(&olb4[i], olb);
    __stcs(&oub4[i], oub);
}

extern "C" void kernel_launch(void* const* d_in, const int* in_sizes, int n_in,
                              void* d_out, int out_size) {
    const float* lb    = (const float*)d_in[0];
    const float* ub    = (const float*)d_in[1];
    const float* alpha = (const float*)d_in[2];
    float* out = (float*)d_out;

    int n  = in_sizes[0];        // 16777216
    int n4 = n / 4;              // 4194304

    float* out_lb = out;
    float* out_ub = out + n;

    int threads = 256;
    int blocks  = (n4 + threads - 1) / threads;   // 16384

    verify_relu_kernel<<<blocks, threads>>>(
        (const float4*)lb, (const float4*)ub, (const float4*)alpha,
        (float4*)out_lb, (float4*)out_ub, n4);
}